// round 14
// baseline (speedup 1.0000x reference)
#include <cuda_runtime.h>
#include <cuda_fp16.h>
#include <cstdint>
#include <cstddef>
#include <cstring>

// Problem constants
#define NMAX 10000
#define EMAX 160000
#define DIN 32
#define DOUT 64
#define DHID 128
#define BFD 13
#define KDIM (DHID * DIN)      // 4096
#define KTOT (KDIM + 2 * DIN)  // 4160 = S | Sx | x
#define NTILES (KTOT / 32)     // 130 k-tiles of 32 halfs

// ---------------- scratch (device globals; no allocations allowed) ------------
__device__ int    g_deg[NMAX];
__device__ int    g_rowptr[NMAX + 1];
__device__ int    g_cursor[NMAX];
__device__ int    g_src[EMAX];
__device__ int    g_dst[EMAX];
__device__ int    g_pos[EMAX];           // edge -> CSR slot
__device__ int    g_csr_src[EMAX];
__device__ __half g_W1t16[DHID * 16];           // B operand: [128 n][16 k]
__device__ __half g_h[(size_t)EMAX * DHID];     // 41 MB, CSR order
__device__ __half g_S[(size_t)NMAX * KDIM];     // 82 MB
__device__ __half g_Sx[(size_t)NMAX * DIN];
__device__ __half g_xh[(size_t)NMAX * DIN];
__device__ __half g_Wt[(size_t)DOUT * KTOT];    // B^T: [64][4160]

// ---------------- small PTX helpers -------------------------------------------
__device__ __forceinline__ uint32_t smem_to_u32(const void* p) {
    uint32_t a;
    asm("{ .reg .u64 t; cvta.to.shared.u64 t, %1; cvt.u32.u64 %0, t; }" : "=r"(a) : "l"(p));
    return a;
}
__device__ __forceinline__ void cp16(uint32_t saddr, const void* g) {
    asm volatile("cp.async.cg.shared.global [%0], [%1], 16;" :: "r"(saddr), "l"(g));
}
#define CP_COMMIT() asm volatile("cp.async.commit_group;" ::: "memory")

__device__ __forceinline__ void mma_f16(float* d, const uint32_t* a, const uint32_t* b) {
    asm volatile("mma.sync.aligned.m16n8k16.row.col.f32.f16.f16.f32 "
        "{%0,%1,%2,%3}, {%4,%5,%6,%7}, {%8,%9}, {%0,%1,%2,%3};"
        : "+f"(d[0]), "+f"(d[1]), "+f"(d[2]), "+f"(d[3])
        : "r"(a[0]), "r"(a[1]), "r"(a[2]), "r"(a[3]), "r"(b[0]), "r"(b[1]));
}
__device__ __forceinline__ void ldmatrix_x4_trans(uint32_t* r, uint32_t saddr) {
    asm volatile("ldmatrix.sync.aligned.m8n8.x4.trans.shared.b16 {%0,%1,%2,%3}, [%4];"
        : "=r"(r[0]), "=r"(r[1]), "=r"(r[2]), "=r"(r[3]) : "r"(saddr));
}
__device__ __forceinline__ uint32_t packh2(float a, float b) {
    __half2 h = __floats2half2_rn(a, b);
    uint32_t r;
    memcpy(&r, &h, 4);
    return r;
}

// ---------------- prep: zero deg, W1 operand, Wt, xh (all independent) --------
__global__ __launch_bounds__(256) void prep_kernel(const float* __restrict__ W1,
                                                   const float* __restrict__ W2,
                                                   const float* __restrict__ b2,
                                                   const float* __restrict__ root,
                                                   const float* __restrict__ x, int N) {
    int i = blockIdx.x * blockDim.x + threadIdx.x;
    int stride = gridDim.x * blockDim.x;
    for (int j = i; j < N; j += stride) g_deg[j] = 0;
    for (int j = i; j < DHID * 16; j += stride) {
        int n = j >> 4, k = j & 15;
        g_W1t16[j] = (k < BFD) ? __float2half_rn(W1[k * DHID + n]) : __float2half_rn(0.f);
    }
    for (int j = i; j < N * DIN; j += stride) g_xh[j] = __float2half_rn(x[j]);
    for (size_t j = i; j < (size_t)DOUT * KTOT; j += stride) {
        int n = (int)(j / KTOT), k = (int)(j % KTOT);
        float v;
        if (k < KDIM)            v = W2[(size_t)k * DOUT + n];
        else if (k < KDIM + DIN) v = b2[(size_t)(k - KDIM) * DOUT + n];
        else                     v = root[(size_t)(k - KDIM - DIN) * DOUT + n];
        g_Wt[j] = __float2half_rn(v);
    }
}

// ---------------- decode + degree count (detect int64 inline) -----------------
__global__ void decode_count_kernel(const void* ei, int E) {
    __shared__ int s64;
    if (threadIdx.x == 0) {
        const int* w = (const int*)ei;
        long long s = 0;
        #pragma unroll 8
        for (int i = 0; i < 64; i++) s += w[2 * i + 1];
        s64 = (s == 0) ? 1 : 0;
    }
    __syncthreads();
    bool is64 = (s64 != 0);
    int i = blockIdx.x * blockDim.x + threadIdx.x;
    int stride = gridDim.x * blockDim.x;
    for (int e = i; e < E; e += stride) {
        int s, d;
        if (is64) {
            const long long* p = (const long long*)ei;
            s = (int)p[e]; d = (int)p[E + e];
        } else {
            const int* p = (const int*)ei;
            s = p[e]; d = p[E + e];
        }
        g_src[e] = s;
        g_dst[e] = d;
        atomicAdd(&g_deg[d], 1);
    }
}

// ---------------- single-block exclusive scan over degrees --------------------
__global__ __launch_bounds__(1024) void scan_kernel(int n) {
    __shared__ int wsum[32];
    __shared__ int carry_s;
    int tid = threadIdx.x, lane = tid & 31, wid = tid >> 5;
    if (tid == 0) carry_s = 0;
    __syncthreads();
    for (int base = 0; base < n; base += 1024) {
        int i = base + tid;
        int v = (i < n) ? g_deg[i] : 0;
        int incl = v;
        #pragma unroll
        for (int d = 1; d < 32; d <<= 1) {
            int y = __shfl_up_sync(0xffffffffu, incl, d);
            if (lane >= d) incl += y;
        }
        if (lane == 31) wsum[wid] = incl;
        __syncthreads();
        if (wid == 0) {
            int s = wsum[lane];
            #pragma unroll
            for (int d = 1; d < 32; d <<= 1) {
                int y = __shfl_up_sync(0xffffffffu, s, d);
                if (lane >= d) s += y;
            }
            wsum[lane] = s;
        }
        __syncthreads();
        int excl = incl - v + ((wid > 0) ? wsum[wid - 1] : 0) + carry_s;
        if (i < n) { g_rowptr[i] = excl; g_cursor[i] = excl; }
        int total = wsum[31];
        __syncthreads();
        if (tid == 0) carry_s += total;
        __syncthreads();
    }
    if (tid == 0) g_rowptr[n] = carry_s;
}

// ---------------- scatter edges into dst-CSR ----------------------------------
__global__ void scatter_kernel(int E) {
    int i = blockIdx.x * blockDim.x + threadIdx.x;
    int stride = gridDim.x * blockDim.x;
    for (int e = i; e < E; e += stride) {
        int d = g_dst[e];
        int pos = atomicAdd(&g_cursor[d], 1);
        g_csr_src[pos] = g_src[e];
        g_pos[e] = pos;
    }
}

// ---------------- h = relu(attr @ W1 + b1), fused attr staging + fp16 MMA -----
// Block = 128 edges (8 warps x 16); attr staged fp32 in smem; h written CSR order.
#define APITCH 14
__global__ __launch_bounds__(256) void hmma_kernel(const float* __restrict__ attr,
                                                   const float* __restrict__ b1, int E) {
    __shared__ float as[128 * APITCH];
    __shared__ int pos_s[128];
    int base = blockIdx.x * 128;
    int cnt = E - base;
    if (cnt <= 0) return;
    if (cnt > 128) cnt = 128;
    int tid = threadIdx.x;
    for (int j = tid; j < cnt * BFD; j += 256) {
        int r = j / BFD, c = j - r * BFD;
        as[r * APITCH + c] = attr[(size_t)base * BFD + j];
    }
    for (int j = tid; j < cnt; j += 256) pos_s[j] = g_pos[base + j];
    __syncthreads();

    int wid = tid >> 5, lane = tid & 31;
    int gid = lane >> 2, tig = lane & 3;
    int e0 = wid * 16;
    if (e0 >= cnt) return;

    uint32_t br[16][2];
    #pragma unroll
    for (int nt = 0; nt < 16; nt++) {
        int n0 = nt * 8 + gid;
        br[nt][0] = *(const uint32_t*)&g_W1t16[n0 * 16 + 2 * tig];
        br[nt][1] = *(const uint32_t*)&g_W1t16[n0 * 16 + 2 * tig + 8];
    }
    int r0 = e0 + gid, r1 = r0 + 8;
    int r0c = (r0 < cnt) ? r0 : cnt - 1;
    int r1c = (r1 < cnt) ? r1 : cnt - 1;
    int cL = 2 * tig, cH = 2 * tig + 8;
    float f0h = (cH < BFD) ? as[r0c * APITCH + cH] : 0.f;
    float f1h = (cH + 1 < BFD) ? as[r0c * APITCH + cH + 1] : 0.f;
    float f2h = (cH < BFD) ? as[r1c * APITCH + cH] : 0.f;
    float f3h = (cH + 1 < BFD) ? as[r1c * APITCH + cH + 1] : 0.f;
    uint32_t a[4];
    a[0] = packh2(as[r0c * APITCH + cL], as[r0c * APITCH + cL + 1]);
    a[1] = packh2(as[r1c * APITCH + cL], as[r1c * APITCH + cL + 1]);
    a[2] = packh2(f0h, f1h);
    a[3] = packh2(f2h, f3h);

    #pragma unroll
    for (int nt = 0; nt < 16; nt++) {
        float c[4] = {0.f, 0.f, 0.f, 0.f};
        mma_f16(c, a, br[nt]);
        int col = nt * 8 + 2 * tig;
        float bb0 = __ldg(&b1[col]), bb1 = __ldg(&b1[col + 1]);
        if (r0 < cnt)
            *(__half2*)&g_h[(size_t)pos_s[r0] * DHID + col] =
                __floats2half2_rn(fmaxf(c[0] + bb0, 0.f), fmaxf(c[1] + bb1, 0.f));
        if (r1 < cnt)
            *(__half2*)&g_h[(size_t)pos_s[r1] * DHID + col] =
                __floats2half2_rn(fmaxf(c[2] + bb0, 0.f), fmaxf(c[3] + bb1, 0.f));
    }
}

// ---------------- tensor-core sbuild: S_n = H_n^T @ X_n per node --------------
#define HPITCH 136
#define XPITCH 24
__global__ __launch_bounds__(128) void sbuild_tc_kernel(int n_nodes) {
    __shared__ __half sh[16 * HPITCH];
    __shared__ __half sx[32 * XPITCH];
    int n = blockIdx.x;
    if (n >= n_nodes) return;
    int tid = threadIdx.x, wid = tid >> 5, lane = tid & 31;
    int gid = lane >> 2, tig = lane & 3;
    uint32_t sh_u = smem_to_u32(sh);

    float acc[2][4][4];
    #pragma unroll
    for (int mt = 0; mt < 2; mt++)
        #pragma unroll
        for (int nt = 0; nt < 4; nt++)
            #pragma unroll
            for (int q = 0; q < 4; q++) acc[mt][nt][q] = 0.f;
    float sxa = 0.f;

    int beg = g_rowptr[n];
    int deg = g_rowptr[n + 1] - beg;

    for (int c0 = 0; c0 < deg; c0 += 16) {
        {
            int r = tid >> 3, s = (tid & 7) * 16;
            uint4 z = make_uint4(0, 0, 0, 0);
            uint4 v0 = z, v1 = z;
            if (c0 + r < deg) {
                const uint4* src = (const uint4*)&g_h[(size_t)(beg + c0 + r) * DHID + s];
                v0 = src[0]; v1 = src[1];
            }
            *(uint4*)&sh[r * HPITCH + s] = v0;
            *(uint4*)&sh[r * HPITCH + s + 8] = v1;
        }
        {
            int j = tid >> 3, ci = (tid & 7) * 4;
            __half vals[4];
            if (c0 + j < deg) {
                int srcn = g_csr_src[beg + c0 + j];
                *(uint2*)vals = *(const uint2*)&g_xh[(size_t)srcn * DIN + ci];
            } else {
                vals[0] = vals[1] = vals[2] = vals[3] = __float2half_rn(0.f);
            }
            #pragma unroll
            for (int q = 0; q < 4; q++) sx[(ci + q) * XPITCH + j] = vals[q];
        }
        __syncthreads();
        if (tid < 32) {
            #pragma unroll
            for (int e2 = 0; e2 < 8; e2++) {
                __half2 hv = *(const __half2*)&sx[tid * XPITCH + 2 * e2];
                float2 f = __half22float2(hv);
                sxa += f.x + f.y;
            }
        }
        uint32_t b[4][2];
        #pragma unroll
        for (int nt = 0; nt < 4; nt++) {
            int irow = nt * 8 + gid;
            b[nt][0] = *(const uint32_t*)&sx[irow * XPITCH + 2 * tig];
            b[nt][1] = *(const uint32_t*)&sx[irow * XPITCH + 2 * tig + 8];
        }
        int grp = lane >> 3, lr = lane & 7;
        int e_l = ((grp & 2) ? 8 : 0) + lr;
        int coff = (grp & 1) ? 8 : 0;
        #pragma unroll
        for (int mt = 0; mt < 2; mt++) {
            int mbase = wid * 32 + mt * 16;
            uint32_t a[4];
            ldmatrix_x4_trans(a, sh_u + (uint32_t)(e_l * HPITCH + mbase + coff) * 2);
            #pragma unroll
            for (int nt = 0; nt < 4; nt++) mma_f16(acc[mt][nt], a, b[nt]);
        }
        __syncthreads();
    }

    #pragma unroll
    for (int mt = 0; mt < 2; mt++) {
        #pragma unroll
        for (int nt = 0; nt < 4; nt++) {
            const float* c = acc[mt][nt];
            int m1 = wid * 32 + mt * 16 + gid;
            int i0 = nt * 8 + 2 * tig;
            *(__half2*)&g_S[(size_t)n * KDIM + m1 * DIN + i0] = __floats2half2_rn(c[0], c[1]);
            *(__half2*)&g_S[(size_t)n * KDIM + (m1 + 8) * DIN + i0] = __floats2half2_rn(c[2], c[3]);
        }
    }
    if (tid < 32) g_Sx[(size_t)n * DIN + tid] = __float2half_rn(sxa);
}

// ---------------- fp16 mma GEMM: out = relu([S|Sx|x] @ Wt^T + bias) -----------
#define MT 64
#define PITCHH 40
#define A_STAGE (MT * PITCHH)
#define B_STAGE (DOUT * PITCHH)
#define STAGE_H (A_STAGE + B_STAGE)
#define NS 3
#define GEMM_SMEM (NS * STAGE_H * 2)

__device__ __forceinline__ void load_tile(int t, uint32_t sAu, uint32_t sBu, int m0, int n_nodes) {
    int tid = threadIdx.x;
    int k0 = t * 32;
    {
        int r = tid >> 2, c0 = (tid & 3) * 8;
        int m = m0 + r;
        if (m >= n_nodes) m = n_nodes - 1;
        const __half* g;
        if (t < 128)       g = g_S  + (size_t)m * KDIM + k0 + c0;
        else if (t == 128) g = g_Sx + (size_t)m * DIN + c0;
        else               g = g_xh + (size_t)m * DIN + c0;
        cp16(sAu + (r * PITCHH + c0) * 2, g);
    }
    {
        int nr = tid >> 2, c0 = (tid & 3) * 8;
        cp16(sBu + (nr * PITCHH + c0) * 2, g_Wt + (size_t)nr * KTOT + k0 + c0);
    }
}

__global__ __launch_bounds__(256) void gemm_mma_kernel(const float* __restrict__ bias,
                                                       float* __restrict__ out, int n_nodes) {
    extern __shared__ __half smem[];
    uint32_t smem_u = smem_to_u32(smem);
    int tid = threadIdx.x, wid = tid >> 5, lane = tid & 31;
    int wm = wid >> 1, wn = wid & 1;
    int gid = lane >> 2, tig = lane & 3;
    int m0 = blockIdx.x * MT;

    float acc[4][4];
    #pragma unroll
    for (int nt = 0; nt < 4; nt++)
        #pragma unroll
        for (int r = 0; r < 4; r++) acc[nt][r] = 0.f;

    #pragma unroll
    for (int t = 0; t < NS - 1; t++) {
        load_tile(t, smem_u + t * STAGE_H * 2, smem_u + (t * STAGE_H + A_STAGE) * 2, m0, n_nodes);
        CP_COMMIT();
    }

    for (int t = 0; t < NTILES; t++) {
        asm volatile("cp.async.wait_group %0;" :: "n"(NS - 2) : "memory");
        __syncthreads();
        int tn = t + NS - 1;
        if (tn < NTILES) {
            int s = tn % NS;
            load_tile(tn, smem_u + s * STAGE_H * 2, smem_u + (s * STAGE_H + A_STAGE) * 2, m0, n_nodes);
        }
        CP_COMMIT();

        const __half* As = smem + (t % NS) * STAGE_H;
        const __half* Bs = As + A_STAGE;
        #pragma unroll
        for (int kc = 0; kc < 2; kc++) {
            int col = kc * 16 + 2 * tig;
            uint32_t a[4];
            {
                int r0 = wm * 16 + gid;
                a[0] = *(const uint32_t*)&As[r0 * PITCHH + col];
                a[1] = *(const uint32_t*)&As[(r0 + 8) * PITCHH + col];
                a[2] = *(const uint32_t*)&As[r0 * PITCHH + col + 8];
                a[3] = *(const uint32_t*)&As[(r0 + 8) * PITCHH + col + 8];
            }
            #pragma unroll
            for (int nt = 0; nt < 4; nt++) {
                int n0 = wn * 32 + nt * 8 + gid;
                uint32_t b[2];
                b[0] = *(const uint32_t*)&Bs[n0 * PITCHH + col];
                b[1] = *(const uint32_t*)&Bs[n0 * PITCHH + col + 8];
                mma_f16(acc[nt], a, b);
            }
        }
        __syncthreads();
    }

    #pragma unroll
    for (int nt = 0; nt < 4; nt++) {
        int o = wn * 32 + nt * 8 + tig * 2;
        float b0 = __ldg(&bias[o]), b1 = __ldg(&bias[o + 1]);
        #pragma unroll
        for (int half_ = 0; half_ < 2; half_++) {
            int n = m0 + wm * 16 + gid + half_ * 8;
            if (n < n_nodes) {
                float2 v;
                v.x = fmaxf(acc[nt][2 * half_ + 0] + b0, 0.f);
                v.y = fmaxf(acc[nt][2 * half_ + 1] + b1, 0.f);
                *(float2*)(out + (size_t)n * DOUT + o) = v;
            }
        }
    }
}

// ---------------- launch ------------------------------------------------------
extern "C" void kernel_launch(void* const* d_in, const int* in_sizes, int n_in,
                              void* d_out, int out_size) {
    const float* x    = (const float*)d_in[0];
    const void*  ei   = d_in[1];
    const float* attr = (const float*)d_in[2];
    const float* W1   = (const float*)d_in[3];
    const float* b1   = (const float*)d_in[4];
    const float* W2   = (const float*)d_in[5];
    const float* b2   = (const float*)d_in[6];
    const float* root = (const float*)d_in[7];
    const float* bias = (const float*)d_in[8];
    float* out = (float*)d_out;

    int N = in_sizes[0] / DIN;
    int E = in_sizes[2] / BFD;
    if (N > NMAX) N = NMAX;
    if (E > EMAX) E = EMAX;

    static int smem_set = 0;
    if (!smem_set) {
        cudaFuncSetAttribute(gemm_mma_kernel, cudaFuncAttributeMaxDynamicSharedMemorySize, GEMM_SMEM);
        smem_set = 1;
    }

    prep_kernel<<<264, 256>>>(W1, W2, b2, root, x, N);
    decode_count_kernel<<<264, 256>>>(ei, E);
    scan_kernel<<<1, 1024>>>(N);
    scatter_kernel<<<264, 256>>>(E);
    hmma_kernel<<<(E + 127) / 128, 256>>>(attr, b1, E);
    sbuild_tc_kernel<<<N, 128>>>(N);
    gemm_mma_kernel<<<(N + MT - 1) / MT, 256, GEMM_SMEM>>>(bias, out, N);
}

// round 15
// speedup vs baseline: 1.4953x; 1.4953x over previous
#include <cuda_runtime.h>
#include <cuda_fp16.h>
#include <cstdint>
#include <cstddef>
#include <cstring>

// Problem constants
#define NMAX 10000
#define EMAX 160000
#define DIN 32
#define DOUT 64
#define DHID 128
#define BFD 13
#define KDIM (DHID * DIN)      // 4096
#define KTOT (KDIM + 2 * DIN)  // 4160 = S | Sx | x
#define NTILES (KTOT / 32)     // 130 k-tiles of 32 halfs

// ---------------- scratch (device globals; no allocations allowed) ------------
__device__ int    g_deg[NMAX];
__device__ int    g_rowptr[NMAX + 1];
__device__ int    g_cursor[NMAX];
__device__ int    g_src[EMAX];
__device__ int    g_dst[EMAX];
__device__ int    g_pos[EMAX];           // edge -> CSR slot
__device__ int    g_csr_src[EMAX];
__device__ __half g_attr16[(size_t)EMAX * 16];  // 5 MB, CSR order, K padded to 16
__device__ __half g_W1t16[DHID * 16];           // B operand: [128 n][16 k]
__device__ __half g_h[(size_t)EMAX * DHID];     // 41 MB, CSR order
__device__ __half g_S[(size_t)NMAX * KDIM];     // 82 MB
__device__ __half g_Sx[(size_t)NMAX * DIN];
__device__ __half g_xh[(size_t)NMAX * DIN];
__device__ __half g_Wt[(size_t)DOUT * KTOT];    // B^T: [64][4160]

// ---------------- small PTX helpers -------------------------------------------
__device__ __forceinline__ uint32_t smem_to_u32(const void* p) {
    uint32_t a;
    asm("{ .reg .u64 t; cvta.to.shared.u64 t, %1; cvt.u32.u64 %0, t; }" : "=r"(a) : "l"(p));
    return a;
}
__device__ __forceinline__ void cp16(uint32_t saddr, const void* g) {
    asm volatile("cp.async.cg.shared.global [%0], [%1], 16;" :: "r"(saddr), "l"(g));
}
#define CP_COMMIT() asm volatile("cp.async.commit_group;" ::: "memory")

__device__ __forceinline__ void mma_f16(float* d, const uint32_t* a, const uint32_t* b) {
    asm volatile("mma.sync.aligned.m16n8k16.row.col.f32.f16.f16.f32 "
        "{%0,%1,%2,%3}, {%4,%5,%6,%7}, {%8,%9}, {%0,%1,%2,%3};"
        : "+f"(d[0]), "+f"(d[1]), "+f"(d[2]), "+f"(d[3])
        : "r"(a[0]), "r"(a[1]), "r"(a[2]), "r"(a[3]), "r"(b[0]), "r"(b[1]));
}
__device__ __forceinline__ void ldmatrix_x4_trans(uint32_t* r, uint32_t saddr) {
    asm volatile("ldmatrix.sync.aligned.m8n8.x4.trans.shared.b16 {%0,%1,%2,%3}, [%4];"
        : "=r"(r[0]), "=r"(r[1]), "=r"(r[2]), "=r"(r[3]) : "r"(saddr));
}

// ---------------- prep: zero deg + W1 operand + xh (all coalesced) ------------
__global__ __launch_bounds__(256) void prep_kernel(const float* __restrict__ W1,
                                                   const float* __restrict__ x, int N) {
    int i = blockIdx.x * blockDim.x + threadIdx.x;
    int stride = gridDim.x * blockDim.x;
    for (int j = i; j < N; j += stride) g_deg[j] = 0;
    for (int j = i; j < DHID * 16; j += stride) {
        int n = j >> 4, k = j & 15;
        g_W1t16[j] = (k < BFD) ? __float2half_rn(W1[k * DHID + n]) : __float2half_rn(0.f);
    }
    for (int j = i; j < N * DIN; j += stride) g_xh[j] = __float2half_rn(x[j]);
}

// ---------------- decode + degree count (detect int64 inline) -----------------
__global__ void decode_count_kernel(const void* ei, int E) {
    __shared__ int s64;
    if (threadIdx.x == 0) {
        const int* w = (const int*)ei;
        long long s = 0;
        #pragma unroll 8
        for (int i = 0; i < 64; i++) s += w[2 * i + 1];
        s64 = (s == 0) ? 1 : 0;
    }
    __syncthreads();
    bool is64 = (s64 != 0);
    int i = blockIdx.x * blockDim.x + threadIdx.x;
    int stride = gridDim.x * blockDim.x;
    for (int e = i; e < E; e += stride) {
        int s, d;
        if (is64) {
            const long long* p = (const long long*)ei;
            s = (int)p[e]; d = (int)p[E + e];
        } else {
            const int* p = (const int*)ei;
            s = p[e]; d = p[E + e];
        }
        g_src[e] = s;
        g_dst[e] = d;
        atomicAdd(&g_deg[d], 1);
    }
}

// ---------------- single-block exclusive scan over degrees --------------------
__global__ __launch_bounds__(1024) void scan_kernel(int n) {
    __shared__ int wsum[32];
    __shared__ int carry_s;
    int tid = threadIdx.x, lane = tid & 31, wid = tid >> 5;
    if (tid == 0) carry_s = 0;
    __syncthreads();
    for (int base = 0; base < n; base += 1024) {
        int i = base + tid;
        int v = (i < n) ? g_deg[i] : 0;
        int incl = v;
        #pragma unroll
        for (int d = 1; d < 32; d <<= 1) {
            int y = __shfl_up_sync(0xffffffffu, incl, d);
            if (lane >= d) incl += y;
        }
        if (lane == 31) wsum[wid] = incl;
        __syncthreads();
        if (wid == 0) {
            int s = wsum[lane];
            #pragma unroll
            for (int d = 1; d < 32; d <<= 1) {
                int y = __shfl_up_sync(0xffffffffu, s, d);
                if (lane >= d) s += y;
            }
            wsum[lane] = s;
        }
        __syncthreads();
        int excl = incl - v + ((wid > 0) ? wsum[wid - 1] : 0) + carry_s;
        if (i < n) { g_rowptr[i] = excl; g_cursor[i] = excl; }
        int total = wsum[31];
        __syncthreads();
        if (tid == 0) carry_s += total;
        __syncthreads();
    }
    if (tid == 0) g_rowptr[n] = carry_s;
}

// ---------------- scatter edges into dst-CSR ----------------------------------
__global__ void scatter_kernel(int E) {
    int i = blockIdx.x * blockDim.x + threadIdx.x;
    int stride = gridDim.x * blockDim.x;
    for (int e = i; e < E; e += stride) {
        int d = g_dst[e];
        int pos = atomicAdd(&g_cursor[d], 1);
        g_csr_src[pos] = g_src[e];
        g_pos[e] = pos;
    }
}

// ---------------- attr -> fp16 [E][16], CSR order -----------------------------
__global__ __launch_bounds__(256) void attr16_kernel(const float* __restrict__ attr, int E) {
    __shared__ float s[256 * BFD];
    int base = blockIdx.x * 256;
    int cnt = E - base;
    if (cnt > 256) cnt = 256;
    if (cnt <= 0) return;
    for (int j = threadIdx.x; j < cnt * BFD; j += 256)
        s[j] = attr[(size_t)base * BFD + j];
    __syncthreads();
    int tid = threadIdx.x;
    if (tid < cnt) {
        int e = base + tid;
        const float* a = s + tid * BFD;
        __half2 p[8];
        #pragma unroll
        for (int q = 0; q < 6; q++) p[q] = __floats2half2_rn(a[2 * q], a[2 * q + 1]);
        p[6] = __floats2half2_rn(a[12], 0.f);
        p[7] = __floats2half2_rn(0.f, 0.f);
        uint4* dst = (uint4*)(g_attr16 + (size_t)g_pos[e] * 16);
        const uint4* ps = (const uint4*)p;
        dst[0] = ps[0];
        dst[1] = ps[1];
    }
}

// ---------------- h = relu(attr16 @ W1t16^T + b1) via m16n8k16 ----------------
__global__ __launch_bounds__(256) void hmma_kernel(const float* __restrict__ b1, int E) {
    int tid = threadIdx.x, wid = tid >> 5, lane = tid & 31;
    int gid = lane >> 2, tig = lane & 3;
    int e0 = (blockIdx.x * 8 + wid) * 16;
    if (e0 >= E) return;
    uint32_t br[16][2];
    #pragma unroll
    for (int nt = 0; nt < 16; nt++) {
        int n0 = nt * 8 + gid;
        br[nt][0] = *(const uint32_t*)&g_W1t16[n0 * 16 + 2 * tig];
        br[nt][1] = *(const uint32_t*)&g_W1t16[n0 * 16 + 2 * tig + 8];
    }
    int r0 = e0 + gid, r1 = r0 + 8;
    int r0c = (r0 < E) ? r0 : E - 1;
    int r1c = (r1 < E) ? r1 : E - 1;
    uint32_t a[4];
    a[0] = *(const uint32_t*)&g_attr16[(size_t)r0c * 16 + 2 * tig];
    a[1] = *(const uint32_t*)&g_attr16[(size_t)r1c * 16 + 2 * tig];
    a[2] = *(const uint32_t*)&g_attr16[(size_t)r0c * 16 + 2 * tig + 8];
    a[3] = *(const uint32_t*)&g_attr16[(size_t)r1c * 16 + 2 * tig + 8];
    #pragma unroll
    for (int nt = 0; nt < 16; nt++) {
        float c[4] = {0.f, 0.f, 0.f, 0.f};
        mma_f16(c, a, br[nt]);
        int col = nt * 8 + 2 * tig;
        float bb0 = __ldg(&b1[col]), bb1 = __ldg(&b1[col + 1]);
        if (r0 < E)
            *(__half2*)&g_h[(size_t)r0 * DHID + col] =
                __floats2half2_rn(fmaxf(c[0] + bb0, 0.f), fmaxf(c[1] + bb1, 0.f));
        if (r1 < E)
            *(__half2*)&g_h[(size_t)r1 * DHID + col] =
                __floats2half2_rn(fmaxf(c[2] + bb0, 0.f), fmaxf(c[3] + bb1, 0.f));
    }
}

// ---------------- build g_Wt[o][k] = B[k][o] (half), B = [W2 | b2 | root] -----
__global__ __launch_bounds__(1024) void wt_kernel(const float* __restrict__ W2,
                                                  const float* __restrict__ b2,
                                                  const float* __restrict__ root) {
    __shared__ float tile[32][33];
    int k0 = blockIdx.x * 32, n0 = blockIdx.y * 32;
    int tx = threadIdx.x, ty = threadIdx.y;
    int k = k0 + ty, n = n0 + tx;
    float v;
    if (k < KDIM)            v = W2[(size_t)k * DOUT + n];
    else if (k < KDIM + DIN) v = b2[(size_t)(k - KDIM) * DOUT + n];
    else                     v = root[(size_t)(k - KDIM - DIN) * DOUT + n];
    tile[ty][tx] = v;
    __syncthreads();
    g_Wt[(size_t)(n0 + ty) * KTOT + k0 + tx] = __float2half_rn(tile[tx][ty]);
}

// ---------------- tensor-core sbuild: S_n = H_n^T @ X_n per node --------------
#define HPITCH 136
#define XPITCH 24
__global__ __launch_bounds__(128) void sbuild_tc_kernel(int n_nodes) {
    __shared__ __half sh[16 * HPITCH];
    __shared__ __half sx[32 * XPITCH];
    int n = blockIdx.x;
    if (n >= n_nodes) return;
    int tid = threadIdx.x, wid = tid >> 5, lane = tid & 31;
    int gid = lane >> 2, tig = lane & 3;
    uint32_t sh_u = smem_to_u32(sh);

    float acc[2][4][4];
    #pragma unroll
    for (int mt = 0; mt < 2; mt++)
        #pragma unroll
        for (int nt = 0; nt < 4; nt++)
            #pragma unroll
            for (int q = 0; q < 4; q++) acc[mt][nt][q] = 0.f;
    float sxa = 0.f;

    int beg = g_rowptr[n];
    int deg = g_rowptr[n + 1] - beg;

    for (int c0 = 0; c0 < deg; c0 += 16) {
        {
            int r = tid >> 3, s = (tid & 7) * 16;
            uint4 z = make_uint4(0, 0, 0, 0);
            uint4 v0 = z, v1 = z;
            if (c0 + r < deg) {
                const uint4* src = (const uint4*)&g_h[(size_t)(beg + c0 + r) * DHID + s];
                v0 = src[0]; v1 = src[1];
            }
            *(uint4*)&sh[r * HPITCH + s] = v0;
            *(uint4*)&sh[r * HPITCH + s + 8] = v1;
        }
        {
            int j = tid >> 3, ci = (tid & 7) * 4;
            __half vals[4];
            if (c0 + j < deg) {
                int srcn = g_csr_src[beg + c0 + j];
                *(uint2*)vals = *(const uint2*)&g_xh[(size_t)srcn * DIN + ci];
            } else {
                vals[0] = vals[1] = vals[2] = vals[3] = __float2half_rn(0.f);
            }
            #pragma unroll
            for (int q = 0; q < 4; q++) sx[(ci + q) * XPITCH + j] = vals[q];
        }
        __syncthreads();
        if (tid < 32) {
            #pragma unroll
            for (int e2 = 0; e2 < 8; e2++) {
                __half2 hv = *(const __half2*)&sx[tid * XPITCH + 2 * e2];
                float2 f = __half22float2(hv);
                sxa += f.x + f.y;
            }
        }
        uint32_t b[4][2];
        #pragma unroll
        for (int nt = 0; nt < 4; nt++) {
            int irow = nt * 8 + gid;
            b[nt][0] = *(const uint32_t*)&sx[irow * XPITCH + 2 * tig];
            b[nt][1] = *(const uint32_t*)&sx[irow * XPITCH + 2 * tig + 8];
        }
        int grp = lane >> 3, lr = lane & 7;
        int e_l = ((grp & 2) ? 8 : 0) + lr;
        int coff = (grp & 1) ? 8 : 0;
        #pragma unroll
        for (int mt = 0; mt < 2; mt++) {
            int mbase = wid * 32 + mt * 16;
            uint32_t a[4];
            ldmatrix_x4_trans(a, sh_u + (uint32_t)(e_l * HPITCH + mbase + coff) * 2);
            #pragma unroll
            for (int nt = 0; nt < 4; nt++) mma_f16(acc[mt][nt], a, b[nt]);
        }
        __syncthreads();
    }

    #pragma unroll
    for (int mt = 0; mt < 2; mt++) {
        #pragma unroll
        for (int nt = 0; nt < 4; nt++) {
            const float* c = acc[mt][nt];
            int m1 = wid * 32 + mt * 16 + gid;
            int i0 = nt * 8 + 2 * tig;
            *(__half2*)&g_S[(size_t)n * KDIM + m1 * DIN + i0] = __floats2half2_rn(c[0], c[1]);
            *(__half2*)&g_S[(size_t)n * KDIM + (m1 + 8) * DIN + i0] = __floats2half2_rn(c[2], c[3]);
        }
    }
    if (tid < 32) g_Sx[(size_t)n * DIN + tid] = __float2half_rn(sxa);
}

// ---------------- fp16 mma GEMM: out = relu([S|Sx|x] @ Wt^T + bias) -----------
#define MT 64
#define PITCHH 40
#define A_STAGE (MT * PITCHH)
#define B_STAGE (DOUT * PITCHH)
#define STAGE_H (A_STAGE + B_STAGE)
#define NS 3
#define GEMM_SMEM (NS * STAGE_H * 2)

__device__ __forceinline__ void load_tile(int t, uint32_t sAu, uint32_t sBu, int m0, int n_nodes) {
    int tid = threadIdx.x;
    int k0 = t * 32;
    {
        int r = tid >> 2, c0 = (tid & 3) * 8;
        int m = m0 + r;
        if (m >= n_nodes) m = n_nodes - 1;
        const __half* g;
        if (t < 128)       g = g_S  + (size_t)m * KDIM + k0 + c0;
        else if (t == 128) g = g_Sx + (size_t)m * DIN + c0;
        else               g = g_xh + (size_t)m * DIN + c0;
        cp16(sAu + (r * PITCHH + c0) * 2, g);
    }
    {
        int nr = tid >> 2, c0 = (tid & 3) * 8;
        cp16(sBu + (nr * PITCHH + c0) * 2, g_Wt + (size_t)nr * KTOT + k0 + c0);
    }
}

__global__ __launch_bounds__(256) void gemm_mma_kernel(const float* __restrict__ bias,
                                                       float* __restrict__ out, int n_nodes) {
    extern __shared__ __half smem[];
    uint32_t smem_u = smem_to_u32(smem);
    int tid = threadIdx.x, wid = tid >> 5, lane = tid & 31;
    int wm = wid >> 1, wn = wid & 1;
    int gid = lane >> 2, tig = lane & 3;
    int m0 = blockIdx.x * MT;

    float acc[4][4];
    #pragma unroll
    for (int nt = 0; nt < 4; nt++)
        #pragma unroll
        for (int r = 0; r < 4; r++) acc[nt][r] = 0.f;

    #pragma unroll
    for (int t = 0; t < NS - 1; t++) {
        load_tile(t, smem_u + t * STAGE_H * 2, smem_u + (t * STAGE_H + A_STAGE) * 2, m0, n_nodes);
        CP_COMMIT();
    }

    for (int t = 0; t < NTILES; t++) {
        asm volatile("cp.async.wait_group %0;" :: "n"(NS - 2) : "memory");
        __syncthreads();
        int tn = t + NS - 1;
        if (tn < NTILES) {
            int s = tn % NS;
            load_tile(tn, smem_u + s * STAGE_H * 2, smem_u + (s * STAGE_H + A_STAGE) * 2, m0, n_nodes);
        }
        CP_COMMIT();

        const __half* As = smem + (t % NS) * STAGE_H;
        const __half* Bs = As + A_STAGE;
        #pragma unroll
        for (int kc = 0; kc < 2; kc++) {
            int col = kc * 16 + 2 * tig;
            uint32_t a[4];
            {
                int r0 = wm * 16 + gid;
                a[0] = *(const uint32_t*)&As[r0 * PITCHH + col];
                a[1] = *(const uint32_t*)&As[(r0 + 8) * PITCHH + col];
                a[2] = *(const uint32_t*)&As[r0 * PITCHH + col + 8];
                a[3] = *(const uint32_t*)&As[(r0 + 8) * PITCHH + col + 8];
            }
            #pragma unroll
            for (int nt = 0; nt < 4; nt++) {
                int n0 = wn * 32 + nt * 8 + gid;
                uint32_t b[2];
                b[0] = *(const uint32_t*)&Bs[n0 * PITCHH + col];
                b[1] = *(const uint32_t*)&Bs[n0 * PITCHH + col + 8];
                mma_f16(acc[nt], a, b);
            }
        }
        __syncthreads();
    }

    #pragma unroll
    for (int nt = 0; nt < 4; nt++) {
        int o = wn * 32 + nt * 8 + tig * 2;
        float b0 = __ldg(&bias[o]), b1 = __ldg(&bias[o + 1]);
        #pragma unroll
        for (int half_ = 0; half_ < 2; half_++) {
            int n = m0 + wm * 16 + gid + half_ * 8;
            if (n < n_nodes) {
                float2 v;
                v.x = fmaxf(acc[nt][2 * half_ + 0] + b0, 0.f);
                v.y = fmaxf(acc[nt][2 * half_ + 1] + b1, 0.f);
                *(float2*)(out + (size_t)n * DOUT + o) = v;
            }
        }
    }
}

// ---------------- launch ------------------------------------------------------
extern "C" void kernel_launch(void* const* d_in, const int* in_sizes, int n_in,
                              void* d_out, int out_size) {
    const float* x    = (const float*)d_in[0];
    const void*  ei   = d_in[1];
    const float* attr = (const float*)d_in[2];
    const float* W1   = (const float*)d_in[3];
    const float* b1   = (const float*)d_in[4];
    const float* W2   = (const float*)d_in[5];
    const float* b2   = (const float*)d_in[6];
    const float* root = (const float*)d_in[7];
    const float* bias = (const float*)d_in[8];
    float* out = (float*)d_out;

    int N = in_sizes[0] / DIN;
    int E = in_sizes[2] / BFD;
    if (N > NMAX) N = NMAX;
    if (E > EMAX) E = EMAX;

    static int smem_set = 0;
    if (!smem_set) {
        cudaFuncSetAttribute(gemm_mma_kernel, cudaFuncAttributeMaxDynamicSharedMemorySize, GEMM_SMEM);
        smem_set = 1;
    }

    prep_kernel<<<264, 256>>>(W1, x, N);
    decode_count_kernel<<<264, 256>>>(ei, E);
    scan_kernel<<<1, 1024>>>(N);
    scatter_kernel<<<264, 256>>>(E);
    attr16_kernel<<<(E + 255) / 256, 256>>>(attr, E);
    wt_kernel<<<dim3(NTILES, 2), dim3(32, 32)>>>(W2, b2, root);
    hmma_kernel<<<(E + 127) / 128, 256>>>(b1, E);
    sbuild_tc_kernel<<<N, 128>>>(N);
    gemm_mma_kernel<<<(N + MT - 1) / MT, 256, GEMM_SMEM>>>(bias, out, N);
}

// round 16
// speedup vs baseline: 1.5862x; 1.0608x over previous
#include <cuda_runtime.h>
#include <cuda_fp16.h>
#include <cstdint>
#include <cstddef>
#include <cstring>

// Problem constants
#define NMAX 10000
#define EMAX 160000
#define DIN 32
#define DOUT 64
#define DHID 128
#define BFD 13
#define KDIM (DHID * DIN)      // 4096
#define KTOT (KDIM + 2 * DIN)  // 4160 = S | Sx | x

// ---------------- scratch (device globals; no allocations allowed) ------------
__device__ int    g_deg[NMAX];
__device__ int    g_rowptr[NMAX + 1];
__device__ int    g_cursor[NMAX];
__device__ int    g_src[EMAX];
__device__ int    g_dst[EMAX];
__device__ int    g_csr_src[EMAX];
__device__ __half g_attr16[(size_t)EMAX * 16];  // 5 MB, CSR order, K padded to 16
__device__ __half g_W1t16[DHID * 16];           // B operand: [128 n][16 k]
__device__ __half g_h[(size_t)EMAX * DHID];     // 41 MB, CSR order
__device__ __half g_S[(size_t)NMAX * KDIM];     // 82 MB
__device__ __half g_Sx[(size_t)NMAX * DIN];
__device__ __half g_xh[(size_t)NMAX * DIN];
__device__ __half g_Wt[(size_t)DOUT * KTOT];    // B^T: [64][4160]

// ---------------- small PTX helpers -------------------------------------------
__device__ __forceinline__ uint32_t smem_to_u32(const void* p) {
    uint32_t a;
    asm("{ .reg .u64 t; cvta.to.shared.u64 t, %1; cvt.u32.u64 %0, t; }" : "=r"(a) : "l"(p));
    return a;
}
__device__ __forceinline__ void cp16(uint32_t saddr, const void* g) {
    asm volatile("cp.async.cg.shared.global [%0], [%1], 16;" :: "r"(saddr), "l"(g));
}
#define CP_COMMIT() asm volatile("cp.async.commit_group;" ::: "memory")

__device__ __forceinline__ void mma_f16(float* d, const uint32_t* a, const uint32_t* b) {
    asm volatile("mma.sync.aligned.m16n8k16.row.col.f32.f16.f16.f32 "
        "{%0,%1,%2,%3}, {%4,%5,%6,%7}, {%8,%9}, {%0,%1,%2,%3};"
        : "+f"(d[0]), "+f"(d[1]), "+f"(d[2]), "+f"(d[3])
        : "r"(a[0]), "r"(a[1]), "r"(a[2]), "r"(a[3]), "r"(b[0]), "r"(b[1]));
}
__device__ __forceinline__ void ldmatrix_x4_trans(uint32_t* r, uint32_t saddr) {
    asm volatile("ldmatrix.sync.aligned.m8n8.x4.trans.shared.b16 {%0,%1,%2,%3}, [%4];"
        : "=r"(r[0]), "=r"(r[1]), "=r"(r[2]), "=r"(r[3]) : "r"(saddr));
}

// ---------------- prep: Wt tiles (blocks <260) + deg/W1t16/xh stripes ---------
__global__ __launch_bounds__(256) void prep_kernel(const float* __restrict__ W1,
                                                   const float* __restrict__ W2,
                                                   const float* __restrict__ b2,
                                                   const float* __restrict__ root,
                                                   const float* __restrict__ x, int N) {
    int b = blockIdx.x;
    if (b < 260) {
        // Wt transpose tile: g_Wt[o][k] = B[k][o], B = [W2 | b2 | root]
        __shared__ float tile[32][33];
        int kt = b % 130, nh = b / 130;
        int k0 = kt * 32, n0 = nh * 32;
        int tx = threadIdx.x & 31, ty0 = threadIdx.x >> 5;
        #pragma unroll
        for (int yy = ty0; yy < 32; yy += 8) {
            int k = k0 + yy, n = n0 + tx;
            float v;
            if (k < KDIM)            v = W2[(size_t)k * DOUT + n];
            else if (k < KDIM + DIN) v = b2[(size_t)(k - KDIM) * DOUT + n];
            else                     v = root[(size_t)(k - KDIM - DIN) * DOUT + n];
            tile[yy][tx] = v;
        }
        __syncthreads();
        #pragma unroll
        for (int yy = ty0; yy < 32; yy += 8)
            g_Wt[(size_t)(n0 + yy) * KTOT + k0 + tx] = __float2half_rn(tile[tx][yy]);
    } else {
        int i = (b - 260) * 256 + threadIdx.x;
        int stride = 264 * 256;
        for (int j = i; j < N; j += stride) g_deg[j] = 0;
        for (int j = i; j < DHID * 16; j += stride) {
            int n = j >> 4, k = j & 15;
            g_W1t16[j] = (k < BFD) ? __float2half_rn(W1[k * DHID + n]) : __float2half_rn(0.f);
        }
        for (int j = i; j < N * DIN; j += stride) g_xh[j] = __float2half_rn(x[j]);
    }
}

// ---------------- decode + degree count (detect int64 inline) -----------------
__global__ void decode_count_kernel(const void* ei, int E) {
    __shared__ int s64;
    if (threadIdx.x == 0) {
        const int* w = (const int*)ei;
        long long s = 0;
        #pragma unroll 8
        for (int i = 0; i < 64; i++) s += w[2 * i + 1];
        s64 = (s == 0) ? 1 : 0;
    }
    __syncthreads();
    bool is64 = (s64 != 0);
    int i = blockIdx.x * blockDim.x + threadIdx.x;
    int stride = gridDim.x * blockDim.x;
    for (int e = i; e < E; e += stride) {
        int s, d;
        if (is64) {
            const long long* p = (const long long*)ei;
            s = (int)p[e]; d = (int)p[E + e];
        } else {
            const int* p = (const int*)ei;
            s = p[e]; d = p[E + e];
        }
        g_src[e] = s;
        g_dst[e] = d;
        atomicAdd(&g_deg[d], 1);
    }
}

// ---------------- single-block exclusive scan over degrees --------------------
__global__ __launch_bounds__(1024) void scan_kernel(int n) {
    __shared__ int wsum[32];
    __shared__ int carry_s;
    int tid = threadIdx.x, lane = tid & 31, wid = tid >> 5;
    if (tid == 0) carry_s = 0;
    __syncthreads();
    for (int base = 0; base < n; base += 1024) {
        int i = base + tid;
        int v = (i < n) ? g_deg[i] : 0;
        int incl = v;
        #pragma unroll
        for (int d = 1; d < 32; d <<= 1) {
            int y = __shfl_up_sync(0xffffffffu, incl, d);
            if (lane >= d) incl += y;
        }
        if (lane == 31) wsum[wid] = incl;
        __syncthreads();
        if (wid == 0) {
            int s = wsum[lane];
            #pragma unroll
            for (int d = 1; d < 32; d <<= 1) {
                int y = __shfl_up_sync(0xffffffffu, s, d);
                if (lane >= d) s += y;
            }
            wsum[lane] = s;
        }
        __syncthreads();
        int excl = incl - v + ((wid > 0) ? wsum[wid - 1] : 0) + carry_s;
        if (i < n) { g_rowptr[i] = excl; g_cursor[i] = excl; }
        int total = wsum[31];
        __syncthreads();
        if (tid == 0) carry_s += total;
        __syncthreads();
    }
    if (tid == 0) g_rowptr[n] = carry_s;
}

// ---------------- scatter + attr16 fused: edges -> CSR slot + attr row --------
__global__ __launch_bounds__(256) void scatter_attr_kernel(const float* __restrict__ attr, int E) {
    __shared__ float s[256 * BFD];
    int base = blockIdx.x * 256;
    int cnt = E - base;
    if (cnt <= 0) return;
    if (cnt > 256) cnt = 256;
    for (int j = threadIdx.x; j < cnt * BFD; j += 256)
        s[j] = attr[(size_t)base * BFD + j];
    __syncthreads();
    int tid = threadIdx.x;
    if (tid < cnt) {
        int e = base + tid;
        int d = g_dst[e];
        int pos = atomicAdd(&g_cursor[d], 1);
        g_csr_src[pos] = g_src[e];
        const float* a = s + tid * BFD;
        __half2 p[8];
        #pragma unroll
        for (int q = 0; q < 6; q++) p[q] = __floats2half2_rn(a[2 * q], a[2 * q + 1]);
        p[6] = __floats2half2_rn(a[12], 0.f);
        p[7] = __floats2half2_rn(0.f, 0.f);
        uint4* dst = (uint4*)(g_attr16 + (size_t)pos * 16);
        const uint4* ps = (const uint4*)p;
        dst[0] = ps[0];
        dst[1] = ps[1];
    }
}

// ---------------- h = relu(attr16 @ W1t16^T + b1) via m16n8k16 ----------------
__global__ __launch_bounds__(256) void hmma_kernel(const float* __restrict__ b1, int E) {
    int tid = threadIdx.x, wid = tid >> 5, lane = tid & 31;
    int gid = lane >> 2, tig = lane & 3;
    int e0 = (blockIdx.x * 8 + wid) * 16;
    if (e0 >= E) return;
    uint32_t br[16][2];
    #pragma unroll
    for (int nt = 0; nt < 16; nt++) {
        int n0 = nt * 8 + gid;
        br[nt][0] = *(const uint32_t*)&g_W1t16[n0 * 16 + 2 * tig];
        br[nt][1] = *(const uint32_t*)&g_W1t16[n0 * 16 + 2 * tig + 8];
    }
    int r0 = e0 + gid, r1 = r0 + 8;
    int r0c = (r0 < E) ? r0 : E - 1;
    int r1c = (r1 < E) ? r1 : E - 1;
    uint32_t a[4];
    a[0] = *(const uint32_t*)&g_attr16[(size_t)r0c * 16 + 2 * tig];
    a[1] = *(const uint32_t*)&g_attr16[(size_t)r1c * 16 + 2 * tig];
    a[2] = *(const uint32_t*)&g_attr16[(size_t)r0c * 16 + 2 * tig + 8];
    a[3] = *(const uint32_t*)&g_attr16[(size_t)r1c * 16 + 2 * tig + 8];
    #pragma unroll
    for (int nt = 0; nt < 16; nt++) {
        float c[4] = {0.f, 0.f, 0.f, 0.f};
        mma_f16(c, a, br[nt]);
        int col = nt * 8 + 2 * tig;
        float bb0 = __ldg(&b1[col]), bb1 = __ldg(&b1[col + 1]);
        if (r0 < E)
            *(__half2*)&g_h[(size_t)r0 * DHID + col] =
                __floats2half2_rn(fmaxf(c[0] + bb0, 0.f), fmaxf(c[1] + bb1, 0.f));
        if (r1 < E)
            *(__half2*)&g_h[(size_t)r1 * DHID + col] =
                __floats2half2_rn(fmaxf(c[2] + bb0, 0.f), fmaxf(c[3] + bb1, 0.f));
    }
}

// ---------------- tensor-core sbuild: S_n = H_n^T @ X_n per node --------------
#define HPITCH 136
#define XPITCH 24
__global__ __launch_bounds__(128) void sbuild_tc_kernel(int n_nodes) {
    __shared__ __half sh[16 * HPITCH];
    __shared__ __half sx[32 * XPITCH];
    int n = blockIdx.x;
    if (n >= n_nodes) return;
    int tid = threadIdx.x, wid = tid >> 5, lane = tid & 31;
    int gid = lane >> 2, tig = lane & 3;
    uint32_t sh_u = smem_to_u32(sh);

    float acc[2][4][4];
    #pragma unroll
    for (int mt = 0; mt < 2; mt++)
        #pragma unroll
        for (int nt = 0; nt < 4; nt++)
            #pragma unroll
            for (int q = 0; q < 4; q++) acc[mt][nt][q] = 0.f;
    float sxa = 0.f;

    int beg = g_rowptr[n];
    int deg = g_rowptr[n + 1] - beg;

    for (int c0 = 0; c0 < deg; c0 += 16) {
        {
            int r = tid >> 3, s = (tid & 7) * 16;
            uint4 z = make_uint4(0, 0, 0, 0);
            uint4 v0 = z, v1 = z;
            if (c0 + r < deg) {
                const uint4* src = (const uint4*)&g_h[(size_t)(beg + c0 + r) * DHID + s];
                v0 = src[0]; v1 = src[1];
            }
            *(uint4*)&sh[r * HPITCH + s] = v0;
            *(uint4*)&sh[r * HPITCH + s + 8] = v1;
        }
        {
            int j = tid >> 3, ci = (tid & 7) * 4;
            __half vals[4];
            if (c0 + j < deg) {
                int srcn = g_csr_src[beg + c0 + j];
                *(uint2*)vals = *(const uint2*)&g_xh[(size_t)srcn * DIN + ci];
            } else {
                vals[0] = vals[1] = vals[2] = vals[3] = __float2half_rn(0.f);
            }
            #pragma unroll
            for (int q = 0; q < 4; q++) sx[(ci + q) * XPITCH + j] = vals[q];
        }
        __syncthreads();
        if (tid < 32) {
            #pragma unroll
            for (int e2 = 0; e2 < 8; e2++) {
                __half2 hv = *(const __half2*)&sx[tid * XPITCH + 2 * e2];
                float2 f = __half22float2(hv);
                sxa += f.x + f.y;
            }
        }
        uint32_t b[4][2];
        #pragma unroll
        for (int nt = 0; nt < 4; nt++) {
            int irow = nt * 8 + gid;
            b[nt][0] = *(const uint32_t*)&sx[irow * XPITCH + 2 * tig];
            b[nt][1] = *(const uint32_t*)&sx[irow * XPITCH + 2 * tig + 8];
        }
        int grp = lane >> 3, lr = lane & 7;
        int e_l = ((grp & 2) ? 8 : 0) + lr;
        int coff = (grp & 1) ? 8 : 0;
        #pragma unroll
        for (int mt = 0; mt < 2; mt++) {
            int mbase = wid * 32 + mt * 16;
            uint32_t a[4];
            ldmatrix_x4_trans(a, sh_u + (uint32_t)(e_l * HPITCH + mbase + coff) * 2);
            #pragma unroll
            for (int nt = 0; nt < 4; nt++) mma_f16(acc[mt][nt], a, b[nt]);
        }
        __syncthreads();
    }

    #pragma unroll
    for (int mt = 0; mt < 2; mt++) {
        #pragma unroll
        for (int nt = 0; nt < 4; nt++) {
            const float* c = acc[mt][nt];
            int m1 = wid * 32 + mt * 16 + gid;
            int i0 = nt * 8 + 2 * tig;
            *(__half2*)&g_S[(size_t)n * KDIM + m1 * DIN + i0] = __floats2half2_rn(c[0], c[1]);
            *(__half2*)&g_S[(size_t)n * KDIM + (m1 + 8) * DIN + i0] = __floats2half2_rn(c[2], c[3]);
        }
    }
    if (tid < 32) g_Sx[(size_t)n * DIN + tid] = __float2half_rn(sxa);
}

// ---------------- fp16 mma GEMM: out = relu([S|Sx|x] @ Wt^T + bias) -----------
// K tiled by 64 halfs (65 tiles), 3-stage cp.async, pitch 72 halfs.
#define MT 64
#define KT2 64
#define NT2 (KTOT / KT2)   // 65
#define PITCH2 72
#define A_STAGE (MT * PITCH2)
#define B_STAGE (DOUT * PITCH2)
#define STAGE_H (A_STAGE + B_STAGE)
#define NS 3
#define GEMM_SMEM (NS * STAGE_H * 2)

__device__ __forceinline__ void load_tile(int t, uint32_t sAu, uint32_t sBu, int m0, int n_nodes) {
    int tid = threadIdx.x;
    int k0 = t * KT2;
    {
        int r = tid >> 2, c0 = (tid & 3) * 16;
        int m = m0 + r;
        if (m >= n_nodes) m = n_nodes - 1;
        const __half* g;
        if (t < 64)       g = g_S + (size_t)m * KDIM + k0 + c0;
        else if (c0 < 32) g = g_Sx + (size_t)m * DIN + c0;
        else              g = g_xh + (size_t)m * DIN + (c0 - 32);
        cp16(sAu + (r * PITCH2 + c0) * 2, g);
        cp16(sAu + (r * PITCH2 + c0 + 8) * 2, g + 8);
    }
    {
        int nr = tid >> 2, c0 = (tid & 3) * 16;
        const __half* g = g_Wt + (size_t)nr * KTOT + k0 + c0;
        cp16(sBu + (nr * PITCH2 + c0) * 2, g);
        cp16(sBu + (nr * PITCH2 + c0 + 8) * 2, g + 8);
    }
}

__global__ __launch_bounds__(256) void gemm_mma_kernel(const float* __restrict__ bias,
                                                       float* __restrict__ out, int n_nodes) {
    extern __shared__ __half smem[];
    uint32_t smem_u = smem_to_u32(smem);
    int tid = threadIdx.x, wid = tid >> 5, lane = tid & 31;
    int wm = wid >> 1, wn = wid & 1;
    int gid = lane >> 2, tig = lane & 3;
    int m0 = blockIdx.x * MT;

    float acc[4][4];
    #pragma unroll
    for (int nt = 0; nt < 4; nt++)
        #pragma unroll
        for (int r = 0; r < 4; r++) acc[nt][r] = 0.f;

    #pragma unroll
    for (int t = 0; t < NS - 1; t++) {
        load_tile(t, smem_u + t * STAGE_H * 2, smem_u + (t * STAGE_H + A_STAGE) * 2, m0, n_nodes);
        CP_COMMIT();
    }

    for (int t = 0; t < NT2; t++) {
        asm volatile("cp.async.wait_group %0;" :: "n"(NS - 2) : "memory");
        __syncthreads();
        int tn = t + NS - 1;
        if (tn < NT2) {
            int s = tn % NS;
            load_tile(tn, smem_u + s * STAGE_H * 2, smem_u + (s * STAGE_H + A_STAGE) * 2, m0, n_nodes);
        }
        CP_COMMIT();

        const __half* As = smem + (t % NS) * STAGE_H;
        const __half* Bs = As + A_STAGE;
        #pragma unroll
        for (int kc = 0; kc < 4; kc++) {
            int col = kc * 16 + 2 * tig;
            uint32_t a[4];
            {
                int r0 = wm * 16 + gid;
                a[0] = *(const uint32_t*)&As[r0 * PITCH2 + col];
                a[1] = *(const uint32_t*)&As[(r0 + 8) * PITCH2 + col];
                a[2] = *(const uint32_t*)&As[r0 * PITCH2 + col + 8];
                a[3] = *(const uint32_t*)&As[(r0 + 8) * PITCH2 + col + 8];
            }
            #pragma unroll
            for (int nt = 0; nt < 4; nt++) {
                int n0 = wn * 32 + nt * 8 + gid;
                uint32_t b[2];
                b[0] = *(const uint32_t*)&Bs[n0 * PITCH2 + col];
                b[1] = *(const uint32_t*)&Bs[n0 * PITCH2 + col + 8];
                mma_f16(acc[nt], a, b);
            }
        }
        __syncthreads();
    }

    #pragma unroll
    for (int nt = 0; nt < 4; nt++) {
        int o = wn * 32 + nt * 8 + tig * 2;
        float b0 = __ldg(&bias[o]), b1 = __ldg(&bias[o + 1]);
        #pragma unroll
        for (int half_ = 0; half_ < 2; half_++) {
            int n = m0 + wm * 16 + gid + half_ * 8;
            if (n < n_nodes) {
                float2 v;
                v.x = fmaxf(acc[nt][2 * half_ + 0] + b0, 0.f);
                v.y = fmaxf(acc[nt][2 * half_ + 1] + b1, 0.f);
                *(float2*)(out + (size_t)n * DOUT + o) = v;
            }
        }
    }
}

// ---------------- launch ------------------------------------------------------
extern "C" void kernel_launch(void* const* d_in, const int* in_sizes, int n_in,
                              void* d_out, int out_size) {
    const float* x    = (const float*)d_in[0];
    const void*  ei   = d_in[1];
    const float* attr = (const float*)d_in[2];
    const float* W1   = (const float*)d_in[3];
    const float* b1   = (const float*)d_in[4];
    const float* W2   = (const float*)d_in[5];
    const float* b2   = (const float*)d_in[6];
    const float* root = (const float*)d_in[7];
    const float* bias = (const float*)d_in[8];
    float* out = (float*)d_out;

    int N = in_sizes[0] / DIN;
    int E = in_sizes[2] / BFD;
    if (N > NMAX) N = NMAX;
    if (E > EMAX) E = EMAX;

    static int smem_set = 0;
    if (!smem_set) {
        cudaFuncSetAttribute(gemm_mma_kernel, cudaFuncAttributeMaxDynamicSharedMemorySize, GEMM_SMEM);
        smem_set = 1;
    }

    prep_kernel<<<524, 256>>>(W1, W2, b2, root, x, N);
    decode_count_kernel<<<264, 256>>>(ei, E);
    scan_kernel<<<1, 1024>>>(N);
    scatter_attr_kernel<<<(E + 255) / 256, 256>>>(attr, E);
    hmma_kernel<<<(E + 127) / 128, 256>>>(b1, E);
    sbuild_tc_kernel<<<N, 128>>>(N);
    gemm_mma_kernel<<<(N + MT - 1) / MT, 256, GEMM_SMEM>>>(bias, out, N);
}

// round 17
// speedup vs baseline: 1.7515x; 1.1042x over previous
#include <cuda_runtime.h>
#include <cuda_fp16.h>
#include <cstdint>
#include <cstddef>
#include <cstring>

// Problem constants
#define NMAX 10000
#define EMAX 160000
#define DIN 32
#define DOUT 64
#define DHID 128
#define BFD 13
#define KDIM (DHID * DIN)      // 4096
#define KTOT (KDIM + 2 * DIN)  // 4160 = S | Sx | x

// ---------------- scratch (device globals; no allocations allowed) ------------
__device__ int    g_deg[NMAX];
__device__ int    g_rowptr[NMAX + 1];
__device__ int    g_cursor[NMAX];
__device__ int    g_src[EMAX];
__device__ int    g_dst[EMAX];
__device__ int    g_csr_src[EMAX];
__device__ __half g_attr16[(size_t)EMAX * 16];  // 5 MB, CSR order, K padded to 16
__device__ __half g_W1t16[DHID * 16];           // B operand: [128 n][16 k]
__device__ __half g_S[(size_t)NMAX * KDIM];     // 82 MB
__device__ __half g_Sx[(size_t)NMAX * DIN];
__device__ __half g_xh[(size_t)NMAX * DIN];
__device__ __half g_Wt[(size_t)DOUT * KTOT];    // B^T: [64][4160]

// ---------------- small PTX helpers -------------------------------------------
__device__ __forceinline__ uint32_t smem_to_u32(const void* p) {
    uint32_t a;
    asm("{ .reg .u64 t; cvta.to.shared.u64 t, %1; cvt.u32.u64 %0, t; }" : "=r"(a) : "l"(p));
    return a;
}
__device__ __forceinline__ void cp16(uint32_t saddr, const void* g) {
    asm volatile("cp.async.cg.shared.global [%0], [%1], 16;" :: "r"(saddr), "l"(g));
}
#define CP_COMMIT() asm volatile("cp.async.commit_group;" ::: "memory")

__device__ __forceinline__ void mma_f16(float* d, const uint32_t* a, const uint32_t* b) {
    asm volatile("mma.sync.aligned.m16n8k16.row.col.f32.f16.f16.f32 "
        "{%0,%1,%2,%3}, {%4,%5,%6,%7}, {%8,%9}, {%0,%1,%2,%3};"
        : "+f"(d[0]), "+f"(d[1]), "+f"(d[2]), "+f"(d[3])
        : "r"(a[0]), "r"(a[1]), "r"(a[2]), "r"(a[3]), "r"(b[0]), "r"(b[1]));
}
__device__ __forceinline__ void ldmatrix_x4_trans(uint32_t* r, uint32_t saddr) {
    asm volatile("ldmatrix.sync.aligned.m8n8.x4.trans.shared.b16 {%0,%1,%2,%3}, [%4];"
        : "=r"(r[0]), "=r"(r[1]), "=r"(r[2]), "=r"(r[3]) : "r"(saddr));
}

// ---------------- prep: Wt tiles (blocks <260) + deg/W1t16/xh stripes ---------
__global__ __launch_bounds__(256) void prep_kernel(const float* __restrict__ W1,
                                                   const float* __restrict__ W2,
                                                   const float* __restrict__ b2,
                                                   const float* __restrict__ root,
                                                   const float* __restrict__ x, int N) {
    int b = blockIdx.x;
    if (b < 260) {
        __shared__ float tile[32][33];
        int kt = b % 130, nh = b / 130;
        int k0 = kt * 32, n0 = nh * 32;
        int tx = threadIdx.x & 31, ty0 = threadIdx.x >> 5;
        #pragma unroll
        for (int yy = ty0; yy < 32; yy += 8) {
            int k = k0 + yy, n = n0 + tx;
            float v;
            if (k < KDIM)            v = W2[(size_t)k * DOUT + n];
            else if (k < KDIM + DIN) v = b2[(size_t)(k - KDIM) * DOUT + n];
            else                     v = root[(size_t)(k - KDIM - DIN) * DOUT + n];
            tile[yy][tx] = v;
        }
        __syncthreads();
        #pragma unroll
        for (int yy = ty0; yy < 32; yy += 8)
            g_Wt[(size_t)(n0 + yy) * KTOT + k0 + tx] = __float2half_rn(tile[tx][yy]);
    } else {
        int i = (b - 260) * 256 + threadIdx.x;
        int stride = 264 * 256;
        for (int j = i; j < N; j += stride) g_deg[j] = 0;
        for (int j = i; j < DHID * 16; j += stride) {
            int n = j >> 4, k = j & 15;
            g_W1t16[j] = (k < BFD) ? __float2half_rn(W1[k * DHID + n]) : __float2half_rn(0.f);
        }
        for (int j = i; j < N * DIN; j += stride) g_xh[j] = __float2half_rn(x[j]);
    }
}

// ---------------- decode + degree count (detect int64 inline) -----------------
__global__ void decode_count_kernel(const void* ei, int E) {
    __shared__ int s64;
    if (threadIdx.x == 0) {
        const int* w = (const int*)ei;
        long long s = 0;
        #pragma unroll 8
        for (int i = 0; i < 64; i++) s += w[2 * i + 1];
        s64 = (s == 0) ? 1 : 0;
    }
    __syncthreads();
    bool is64 = (s64 != 0);
    int i = blockIdx.x * blockDim.x + threadIdx.x;
    int stride = gridDim.x * blockDim.x;
    for (int e = i; e < E; e += stride) {
        int s, d;
        if (is64) {
            const long long* p = (const long long*)ei;
            s = (int)p[e]; d = (int)p[E + e];
        } else {
            const int* p = (const int*)ei;
            s = p[e]; d = p[E + e];
        }
        g_src[e] = s;
        g_dst[e] = d;
        atomicAdd(&g_deg[d], 1);
    }
}

// ---------------- single-block exclusive scan over degrees --------------------
__global__ __launch_bounds__(1024) void scan_kernel(int n) {
    __shared__ int wsum[32];
    __shared__ int carry_s;
    int tid = threadIdx.x, lane = tid & 31, wid = tid >> 5;
    if (tid == 0) carry_s = 0;
    __syncthreads();
    for (int base = 0; base < n; base += 1024) {
        int i = base + tid;
        int v = (i < n) ? g_deg[i] : 0;
        int incl = v;
        #pragma unroll
        for (int d = 1; d < 32; d <<= 1) {
            int y = __shfl_up_sync(0xffffffffu, incl, d);
            if (lane >= d) incl += y;
        }
        if (lane == 31) wsum[wid] = incl;
        __syncthreads();
        if (wid == 0) {
            int s = wsum[lane];
            #pragma unroll
            for (int d = 1; d < 32; d <<= 1) {
                int y = __shfl_up_sync(0xffffffffu, s, d);
                if (lane >= d) s += y;
            }
            wsum[lane] = s;
        }
        __syncthreads();
        int excl = incl - v + ((wid > 0) ? wsum[wid - 1] : 0) + carry_s;
        if (i < n) { g_rowptr[i] = excl; g_cursor[i] = excl; }
        int total = wsum[31];
        __syncthreads();
        if (tid == 0) carry_s += total;
        __syncthreads();
    }
    if (tid == 0) g_rowptr[n] = carry_s;
}

// ---------------- scatter + attr16 fused: edges -> CSR slot + attr row --------
__global__ __launch_bounds__(256) void scatter_attr_kernel(const float* __restrict__ attr, int E) {
    __shared__ float s[256 * BFD];
    int base = blockIdx.x * 256;
    int cnt = E - base;
    if (cnt <= 0) return;
    if (cnt > 256) cnt = 256;
    for (int j = threadIdx.x; j < cnt * BFD; j += 256)
        s[j] = attr[(size_t)base * BFD + j];
    __syncthreads();
    int tid = threadIdx.x;
    if (tid < cnt) {
        int e = base + tid;
        int d = g_dst[e];
        int pos = atomicAdd(&g_cursor[d], 1);
        g_csr_src[pos] = g_src[e];
        const float* a = s + tid * BFD;
        __half2 p[8];
        #pragma unroll
        for (int q = 0; q < 6; q++) p[q] = __floats2half2_rn(a[2 * q], a[2 * q + 1]);
        p[6] = __floats2half2_rn(a[12], 0.f);
        p[7] = __floats2half2_rn(0.f, 0.f);
        uint4* dst = (uint4*)(g_attr16 + (size_t)pos * 16);
        const uint4* ps = (const uint4*)p;
        dst[0] = ps[0];
        dst[1] = ps[1];
    }
}

// ---------------- fused sbuild: h on-the-fly + S_n = H_n^T @ X_n --------------
// CTA = 1 node, 4 warps; warp w owns h-cols w*32..+31. Chunks of 16 edges.
// h chunk computed via m16n8k16 from attr16 (CSR-contiguous) + register W1t16,
// stored to sh as fp16 (same rounding as the old hmma), then consumed by
// ldmatrix.trans exactly as before. g_h eliminated.
#define HPITCH 136
#define XPITCH 24
__global__ __launch_bounds__(128) void sbuild_fused_kernel(const float* __restrict__ b1,
                                                           int n_nodes) {
    __shared__ __half sh[16 * HPITCH];
    __shared__ __half sx[32 * XPITCH];
    int n = blockIdx.x;
    if (n >= n_nodes) return;
    int tid = threadIdx.x, wid = tid >> 5, lane = tid & 31;
    int gid = lane >> 2, tig = lane & 3;
    uint32_t sh_u = smem_to_u32(sh);

    // W1 fragments + bias for this warp's 32 h-cols (loop-invariant)
    uint32_t bw[4][2];
    float bb0[4], bb1[4];
    #pragma unroll
    for (int nt = 0; nt < 4; nt++) {
        int n0 = wid * 32 + nt * 8 + gid;
        bw[nt][0] = *(const uint32_t*)&g_W1t16[n0 * 16 + 2 * tig];
        bw[nt][1] = *(const uint32_t*)&g_W1t16[n0 * 16 + 2 * tig + 8];
        int col = wid * 32 + nt * 8 + 2 * tig;
        bb0[nt] = __ldg(&b1[col]);
        bb1[nt] = __ldg(&b1[col + 1]);
    }

    float acc[2][4][4];
    #pragma unroll
    for (int mt = 0; mt < 2; mt++)
        #pragma unroll
        for (int nt = 0; nt < 4; nt++)
            #pragma unroll
            for (int q = 0; q < 4; q++) acc[mt][nt][q] = 0.f;
    float sxa = 0.f;

    int beg = g_rowptr[n];
    int deg = g_rowptr[n + 1] - beg;
    const __half2 hz = __floats2half2_rn(0.f, 0.f);

    for (int c0 = 0; c0 < deg; c0 += 16) {
        // ---- compute h tile [16 edges x 128 cols] into sh ----
        int r0 = c0 + gid, r1 = r0 + 8;
        size_t p0 = (size_t)(beg + ((r0 < deg) ? r0 : 0)) * 16;
        size_t p1 = (size_t)(beg + ((r1 < deg) ? r1 : 0)) * 16;
        uint32_t a[4];
        a[0] = *(const uint32_t*)&g_attr16[p0 + 2 * tig];
        a[1] = *(const uint32_t*)&g_attr16[p1 + 2 * tig];
        a[2] = *(const uint32_t*)&g_attr16[p0 + 2 * tig + 8];
        a[3] = *(const uint32_t*)&g_attr16[p1 + 2 * tig + 8];
        #pragma unroll
        for (int nt = 0; nt < 4; nt++) {
            float c[4] = {0.f, 0.f, 0.f, 0.f};
            mma_f16(c, a, bw[nt]);
            int col = wid * 32 + nt * 8 + 2 * tig;
            __half2 h0 = (r0 < deg)
                ? __floats2half2_rn(fmaxf(c[0] + bb0[nt], 0.f), fmaxf(c[1] + bb1[nt], 0.f)) : hz;
            __half2 h1 = (r1 < deg)
                ? __floats2half2_rn(fmaxf(c[2] + bb0[nt], 0.f), fmaxf(c[3] + bb1[nt], 0.f)) : hz;
            *(__half2*)&sh[gid * HPITCH + col] = h0;
            *(__half2*)&sh[(gid + 8) * HPITCH + col] = h1;
        }
        // ---- gather Xt [32 i x 16 e] ----
        {
            int j = tid >> 3, ci = (tid & 7) * 4;
            __half vals[4];
            if (c0 + j < deg) {
                int srcn = g_csr_src[beg + c0 + j];
                *(uint2*)vals = *(const uint2*)&g_xh[(size_t)srcn * DIN + ci];
            } else {
                vals[0] = vals[1] = vals[2] = vals[3] = __float2half_rn(0.f);
            }
            #pragma unroll
            for (int q = 0; q < 4; q++) sx[(ci + q) * XPITCH + j] = vals[q];
        }
        __syncthreads();
        // Sx partial
        if (tid < 32) {
            #pragma unroll
            for (int e2 = 0; e2 < 8; e2++) {
                __half2 hv = *(const __half2*)&sx[tid * XPITCH + 2 * e2];
                float2 f = __half22float2(hv);
                sxa += f.x + f.y;
            }
        }
        // B fragments from Xt
        uint32_t b[4][2];
        #pragma unroll
        for (int nt = 0; nt < 4; nt++) {
            int irow = nt * 8 + gid;
            b[nt][0] = *(const uint32_t*)&sx[irow * XPITCH + 2 * tig];
            b[nt][1] = *(const uint32_t*)&sx[irow * XPITCH + 2 * tig + 8];
        }
        // A fragments via ldmatrix.trans, then MMA
        int grp = lane >> 3, lr = lane & 7;
        int e_l = ((grp & 2) ? 8 : 0) + lr;
        int coff = (grp & 1) ? 8 : 0;
        #pragma unroll
        for (int mt = 0; mt < 2; mt++) {
            int mbase = wid * 32 + mt * 16;
            uint32_t af[4];
            ldmatrix_x4_trans(af, sh_u + (uint32_t)(e_l * HPITCH + mbase + coff) * 2);
            #pragma unroll
            for (int nt = 0; nt < 4; nt++) mma_f16(acc[mt][nt], af, b[nt]);
        }
        __syncthreads();
    }

    #pragma unroll
    for (int mt = 0; mt < 2; mt++) {
        #pragma unroll
        for (int nt = 0; nt < 4; nt++) {
            const float* c = acc[mt][nt];
            int m1 = wid * 32 + mt * 16 + gid;
            int i0 = nt * 8 + 2 * tig;
            *(__half2*)&g_S[(size_t)n * KDIM + m1 * DIN + i0] = __floats2half2_rn(c[0], c[1]);
            *(__half2*)&g_S[(size_t)n * KDIM + (m1 + 8) * DIN + i0] = __floats2half2_rn(c[2], c[3]);
        }
    }
    if (tid < 32) g_Sx[(size_t)n * DIN + tid] = __float2half_rn(sxa);
}

// ---------------- fp16 mma GEMM: out = relu([S|Sx|x] @ Wt^T + bias) -----------
// K tiled by 64 halfs (65 tiles), 3-stage cp.async, pitch 72 halfs.
#define MT 64
#define KT2 64
#define NT2 (KTOT / KT2)   // 65
#define PITCH2 72
#define A_STAGE (MT * PITCH2)
#define B_STAGE (DOUT * PITCH2)
#define STAGE_H (A_STAGE + B_STAGE)
#define NS 3
#define GEMM_SMEM (NS * STAGE_H * 2)

__device__ __forceinline__ void load_tile(int t, uint32_t sAu, uint32_t sBu, int m0, int n_nodes) {
    int tid = threadIdx.x;
    int k0 = t * KT2;
    {
        int r = tid >> 2, c0 = (tid & 3) * 16;
        int m = m0 + r;
        if (m >= n_nodes) m = n_nodes - 1;
        const __half* g;
        if (t < 64)       g = g_S + (size_t)m * KDIM + k0 + c0;
        else if (c0 < 32) g = g_Sx + (size_t)m * DIN + c0;
        else              g = g_xh + (size_t)m * DIN + (c0 - 32);
        cp16(sAu + (r * PITCH2 + c0) * 2, g);
        cp16(sAu + (r * PITCH2 + c0 + 8) * 2, g + 8);
    }
    {
        int nr = tid >> 2, c0 = (tid & 3) * 16;
        const __half* g = g_Wt + (size_t)nr * KTOT + k0 + c0;
        cp16(sBu + (nr * PITCH2 + c0) * 2, g);
        cp16(sBu + (nr * PITCH2 + c0 + 8) * 2, g + 8);
    }
}

__global__ __launch_bounds__(256) void gemm_mma_kernel(const float* __restrict__ bias,
                                                       float* __restrict__ out, int n_nodes) {
    extern __shared__ __half smem[];
    uint32_t smem_u = smem_to_u32(smem);
    int tid = threadIdx.x, wid = tid >> 5, lane = tid & 31;
    int wm = wid >> 1, wn = wid & 1;
    int gid = lane >> 2, tig = lane & 3;
    int m0 = blockIdx.x * MT;

    float acc[4][4];
    #pragma unroll
    for (int nt = 0; nt < 4; nt++)
        #pragma unroll
        for (int r = 0; r < 4; r++) acc[nt][r] = 0.f;

    #pragma unroll
    for (int t = 0; t < NS - 1; t++) {
        load_tile(t, smem_u + t * STAGE_H * 2, smem_u + (t * STAGE_H + A_STAGE) * 2, m0, n_nodes);
        CP_COMMIT();
    }

    for (int t = 0; t < NT2; t++) {
        asm volatile("cp.async.wait_group %0;" :: "n"(NS - 2) : "memory");
        __syncthreads();
        int tn = t + NS - 1;
        if (tn < NT2) {
            int s = tn % NS;
            load_tile(tn, smem_u + s * STAGE_H * 2, smem_u + (s * STAGE_H + A_STAGE) * 2, m0, n_nodes);
        }
        CP_COMMIT();

        const __half* As = smem + (t % NS) * STAGE_H;
        const __half* Bs = As + A_STAGE;
        #pragma unroll
        for (int kc = 0; kc < 4; kc++) {
            int col = kc * 16 + 2 * tig;
            uint32_t a[4];
            {
                int r0 = wm * 16 + gid;
                a[0] = *(const uint32_t*)&As[r0 * PITCH2 + col];
                a[1] = *(const uint32_t*)&As[(r0 + 8) * PITCH2 + col];
                a[2] = *(const uint32_t*)&As[r0 * PITCH2 + col + 8];
                a[3] = *(const uint32_t*)&As[(r0 + 8) * PITCH2 + col + 8];
            }
            #pragma unroll
            for (int nt = 0; nt < 4; nt++) {
                int n0 = wn * 32 + nt * 8 + gid;
                uint32_t b[2];
                b[0] = *(const uint32_t*)&Bs[n0 * PITCH2 + col];
                b[1] = *(const uint32_t*)&Bs[n0 * PITCH2 + col + 8];
                mma_f16(acc[nt], a, b);
            }
        }
        __syncthreads();
    }

    #pragma unroll
    for (int nt = 0; nt < 4; nt++) {
        int o = wn * 32 + nt * 8 + tig * 2;
        float b0 = __ldg(&bias[o]), b1 = __ldg(&bias[o + 1]);
        #pragma unroll
        for (int half_ = 0; half_ < 2; half_++) {
            int n = m0 + wm * 16 + gid + half_ * 8;
            if (n < n_nodes) {
                float2 v;
                v.x = fmaxf(acc[nt][2 * half_ + 0] + b0, 0.f);
                v.y = fmaxf(acc[nt][2 * half_ + 1] + b1, 0.f);
                *(float2*)(out + (size_t)n * DOUT + o) = v;
            }
        }
    }
}

// ---------------- launch ------------------------------------------------------
extern "C" void kernel_launch(void* const* d_in, const int* in_sizes, int n_in,
                              void* d_out, int out_size) {
    const float* x    = (const float*)d_in[0];
    const void*  ei   = d_in[1];
    const float* attr = (const float*)d_in[2];
    const float* W1   = (const float*)d_in[3];
    const float* b1   = (const float*)d_in[4];
    const float* W2   = (const float*)d_in[5];
    const float* b2   = (const float*)d_in[6];
    const float* root = (const float*)d_in[7];
    const float* bias = (const float*)d_in[8];
    float* out = (float*)d_out;

    int N = in_sizes[0] / DIN;
    int E = in_sizes[2] / BFD;
    if (N > NMAX) N = NMAX;
    if (E > EMAX) E = EMAX;

    static int smem_set = 0;
    if (!smem_set) {
        cudaFuncSetAttribute(gemm_mma_kernel, cudaFuncAttributeMaxDynamicSharedMemorySize, GEMM_SMEM);
        smem_set = 1;
    }

    prep_kernel<<<524, 256>>>(W1, W2, b2, root, x, N);
    decode_count_kernel<<<264, 256>>>(ei, E);
    scan_kernel<<<1, 1024>>>(N);
    scatter_attr_kernel<<<(E + 255) / 256, 256>>>(attr, E);
    sbuild_fused_kernel<<<N, 128>>>(b1, N);
    gemm_mma_kernel<<<(N + MT - 1) / MT, 256, GEMM_SMEM>>>(bias, out, N);
}